// round 16
// baseline (speedup 1.0000x reference)
#include <cuda_runtime.h>
#include <math.h>

// ---------------- problem constants ----------------
#define NB    32
#define NCOL  160
#define NOUT  10
#define OFF_DIST 320
#define OFF_PROB 5440
#define OFF_LOSS 10560

#define NT    512
#define BPB   9                   // blocks per batch
#define NBLK  (NB*BPB)            // 288
#define NWT   119                 // warp-tickets per batch (119*32 = 3808 >= 3800 items)
#define NITEM 3800

// smem layout (words)
#define SXSTR 532                 // validated R13: c*532 %32 = 20c -> conflict-free; max x idx 527
#define SXW   (8*SXSTR)           // 4256
// w regions (T=16 needs WW >= L+4, mult of 4, WW%32 != 0)
#define SW3   0                   // L=256, WW=260 (260%32=4)
#define SW2   10400               // L=154, WW=164 (164%32=4)
#define SW1   16960               // L=103, WW=108 (108%32=12)
#define SW0   21280               // L=52,  WW=60  (60%32=28)
#define SWTOT 23680
#define SRED  (SXW + SWTOT)       // 27936
#define SM_WORDS (SRED + 320)     // 28256
#define SM_BYTES (SM_WORDS*4)     // 113024 B -> 2 blocks/SM at 512 threads

// item space per batch (expensive-first): set3 [0,680) set2 [680,1600) set1 [1600,2640) set0 [2640,3800)
#define I3 680
#define I2 1600
#define I1 2640

__device__ unsigned g_d[NB*NCOL] = {};
__device__ unsigned g_q[NB*NCOL] = {};
__device__ unsigned g_wt[NB] = {};
__device__ unsigned g_ctr = 0;

__device__ __forceinline__ unsigned fenc(float f){unsigned u=__float_as_uint(f);return (u&0x80000000u)?~u:(u|0x80000000u);}
__device__ __forceinline__ float fdec(unsigned e){unsigned u=(e&0x80000000u)?(e&0x7fffffffu):~e;return __uint_as_float(u);}
__device__ __forceinline__ unsigned ienc(float f){ return ~fenc(f); }   // max(ienc)=min(f); 0 sentinel
__device__ __forceinline__ float idec(unsigned e){ return fdec(~e); }

// ring rotations (compile-time renaming, no MOVs)
#define R0  x0,x1,x2,x3,x4,x5,x6,x7,x8,x9,x10,x11,x12,x13,x14,x15
#define R1  x1,x2,x3,x4,x5,x6,x7,x8,x9,x10,x11,x12,x13,x14,x15,x0
#define R2  x2,x3,x4,x5,x6,x7,x8,x9,x10,x11,x12,x13,x14,x15,x0,x1
#define R3  x3,x4,x5,x6,x7,x8,x9,x10,x11,x12,x13,x14,x15,x0,x1,x2
#define R4  x4,x5,x6,x7,x8,x9,x10,x11,x12,x13,x14,x15,x0,x1,x2,x3
#define R5  x5,x6,x7,x8,x9,x10,x11,x12,x13,x14,x15,x0,x1,x2,x3,x4
#define R6  x6,x7,x8,x9,x10,x11,x12,x13,x14,x15,x0,x1,x2,x3,x4,x5
#define R7  x7,x8,x9,x10,x11,x12,x13,x14,x15,x0,x1,x2,x3,x4,x5,x6
#define R8  x8,x9,x10,x11,x12,x13,x14,x15,x0,x1,x2,x3,x4,x5,x6,x7
#define R9  x9,x10,x11,x12,x13,x14,x15,x0,x1,x2,x3,x4,x5,x6,x7,x8
#define R10 x10,x11,x12,x13,x14,x15,x0,x1,x2,x3,x4,x5,x6,x7,x8,x9
#define R11 x11,x12,x13,x14,x15,x0,x1,x2,x3,x4,x5,x6,x7,x8,x9,x10
#define R12 x12,x13,x14,x15,x0,x1,x2,x3,x4,x5,x6,x7,x8,x9,x10,x11
#define R13 x13,x14,x15,x0,x1,x2,x3,x4,x5,x6,x7,x8,x9,x10,x11,x12
#define R14 x14,x15,x0,x1,x2,x3,x4,x5,x6,x7,x8,x9,x10,x11,x12,x13
#define R15 x15,x0,x1,x2,x3,x4,x5,x6,x7,x8,x9,x10,x11,x12,x13,x14

#define STEP2(W,JJ,a0,a1,a2,a3,a4,a5,a6,a7,a8,a9,aA,aB,aC,aD,aE,aF) do { \
    float w_ = (W); \
    acc0  += fabsf(a0 - w_);  acc1  += fabsf(a1 - w_); \
    acc2  += fabsf(a2 - w_);  acc3  += fabsf(a3 - w_); \
    acc4  += fabsf(a4 - w_);  acc5  += fabsf(a5 - w_); \
    acc6  += fabsf(a6 - w_);  acc7  += fabsf(a7 - w_); \
    acc8  += fabsf(a8 - w_);  acc9  += fabsf(a9 - w_); \
    acc10 += fabsf(aA - w_);  acc11 += fabsf(aB - w_); \
    acc12 += fabsf(aC - w_);  acc13 += fabsf(aD - w_); \
    acc14 += fabsf(aE - w_);  acc15 += fabsf(aF - w_); \
    a0 = xr[(JJ) + 16]; \
} while (0)
#define STEP(W, JJ, RING) STEP2(W, JJ, RING)

#define FIN(K, A) do { \
    int mm = 16*tl + (K); \
    if (mm < M) { \
        float d_ = (A) * INVL * __ldg(&pr[mm]); \
        dmin = fminf(dmin, d_); \
        qmin = fminf(qmin, fabsf(d_)); \
    } \
} while (0)

// ---------------- one item = 16 consecutive windows (validated R13 core) ----------------
template<int L, int M, int WW, int SBASE>
__device__ __forceinline__ void item1(const float* __restrict__ sx, const float* __restrict__ swr,
                                      const float* __restrict__ pcm,
                                      unsigned* __restrict__ sden, unsigned* __restrict__ sq, int local)
{
    constexpr int MAIN = L & ~15;
    constexpr int REM  = L & 15;
    constexpr float INVL = 1.0f/(float)L;

    int tl = local / 40;
    int nc = local - tl*40;
    int c  = nc & 7;
    const float* xr = sx + c*SXSTR + 16*tl;
    const float* wr = swr + nc*WW;

    float4 xa = *(const float4*)(xr);
    float4 xb = *(const float4*)(xr + 4);
    float4 xc = *(const float4*)(xr + 8);
    float4 xd = *(const float4*)(xr + 12);
    float x0=xa.x,x1=xa.y,x2=xa.z,x3=xa.w, x4=xb.x,x5=xb.y,x6=xb.z,x7=xb.w;
    float x8=xc.x,x9=xc.y,x10=xc.z,x11=xc.w, x12=xd.x,x13=xd.y,x14=xd.z,x15=xd.w;
    float acc0=0.f,acc1=0.f,acc2=0.f,acc3=0.f,acc4=0.f,acc5=0.f,acc6=0.f,acc7=0.f;
    float acc8=0.f,acc9=0.f,acc10=0.f,acc11=0.f,acc12=0.f,acc13=0.f,acc14=0.f,acc15=0.f;

    float4 wA = *(const float4*)(wr);
    for (int j = 0; j < MAIN; j += 16) {
        float4 wB = *(const float4*)(wr + j + 4);
        STEP(wA.x, j+0,  R0);  STEP(wA.y, j+1,  R1);  STEP(wA.z, j+2,  R2);  STEP(wA.w, j+3,  R3);
        float4 wC = *(const float4*)(wr + j + 8);
        STEP(wB.x, j+4,  R4);  STEP(wB.y, j+5,  R5);  STEP(wB.z, j+6,  R6);  STEP(wB.w, j+7,  R7);
        float4 wD = *(const float4*)(wr + j + 12);
        STEP(wC.x, j+8,  R8);  STEP(wC.y, j+9,  R9);  STEP(wC.z, j+10, R10); STEP(wC.w, j+11, R11);
        wA = *(const float4*)(wr + j + 16);   // safe: WW >= L+4
        STEP(wD.x, j+12, R12); STEP(wD.y, j+13, R13); STEP(wD.z, j+14, R14); STEP(wD.w, j+15, R15);
    }
    if (REM > 0) {                            // wA holds wr[MAIN..MAIN+3]
        STEP(wA.x, MAIN+0, R0);
        if (REM > 1) STEP(wA.y, MAIN+1, R1);
        if (REM > 2) STEP(wA.z, MAIN+2, R2);
        if (REM > 3) STEP(wA.w, MAIN+3, R3);
    }
    if (REM > 4) {
        float4 v = *(const float4*)(wr + MAIN + 4);
        STEP(v.x, MAIN+4, R4);
        if (REM > 5) STEP(v.y, MAIN+5, R5);
        if (REM > 6) STEP(v.z, MAIN+6, R6);
        if (REM > 7) STEP(v.w, MAIN+7, R7);
    }
    if (REM > 8) {
        float4 v = *(const float4*)(wr + MAIN + 8);
        STEP(v.x, MAIN+8, R8);
        if (REM > 9)  STEP(v.y, MAIN+9,  R9);
        if (REM > 10) STEP(v.z, MAIN+10, R10);
        if (REM > 11) STEP(v.w, MAIN+11, R11);
    }
    if (REM > 12) {
        float4 v = *(const float4*)(wr + MAIN + 12);
        STEP(v.x, MAIN+12, R12);
        if (REM > 13) STEP(v.y, MAIN+13, R13);
        if (REM > 14) STEP(v.z, MAIN+14, R14);
    }

    const float* pr = pcm + c*M;
    float dmin = 3.4e38f, qmin = 3.4e38f;
    FIN(0,acc0);   FIN(1,acc1);   FIN(2,acc2);   FIN(3,acc3);
    FIN(4,acc4);   FIN(5,acc5);   FIN(6,acc6);   FIN(7,acc7);
    FIN(8,acc8);   FIN(9,acc9);   FIN(10,acc10); FIN(11,acc11);
    FIN(12,acc12); FIN(13,acc13); FIN(14,acc14); FIN(15,acc15);

    atomicMax(&sden[SBASE + nc], ienc(dmin));
    atomicMax(&sq[SBASE + nc],   ienc(qmin));
}

template<int L, int WW>
__device__ __forceinline__ void stage_w(float* __restrict__ dst, const float* __restrict__ wp, int tid) {
    for (int i2 = tid; i2 < 40*L; i2 += NT) {
        int r = i2 / L, j = i2 - r*L;
        dst[r*WW + j] = wp[i2];
    }
}

// ---------------- fused persistent kernel ----------------
__global__ __launch_bounds__(NT, 2)
void k_all(const float* __restrict__ x,
           const float* __restrict__ w0, const float* __restrict__ w1,
           const float* __restrict__ w2, const float* __restrict__ w3,
           const float* __restrict__ p0, const float* __restrict__ p1,
           const float* __restrict__ p2, const float* __restrict__ p3,
           const float* __restrict__ Wout, float* __restrict__ out)
{
    extern __shared__ float sm[];
    float* sx = sm;
    float* sw = sm + SXW;
    unsigned* sden = (unsigned*)(sm + SRED);   // [160]
    unsigned* sq   = sden + 160;               // [160]
    __shared__ unsigned s_old;

    int tid = threadIdx.x;
    int bx = blockIdx.x;
    int b = bx / BPB;

    if (tid < 320) sden[tid] = 0u;             // sden + sq

    // ---- block 0: losses first (uses sm[0..2304) only; x/w staged after) ----
    if (bx == 0) {
        float* sf   = sm;            // [640]
        float* sr   = sm + 640;      // [640]
        float* sval = sm + 1280;     // [512]
        float* sreg = sm + 1792;     // [512]

        float reg = 0.f;
        for (int i = tid; i < NOUT*NCOL; i += NT) reg += fabsf(Wout[i]);
        sreg[tid] = reg;

        const int Ls[4] = {52, 103, 154, 256};
        const float* wls[4] = {w0, w1, w2, w3};
        const signed char I1a[10] = {0,0,0,0,1,1,1,2,2,3};
        const signed char J1a[10] = {1,2,3,4,2,3,4,3,4,4};

        for (int u = tid; u < 640; u += NT) {
            int pp = u >> 1, h = u & 1;
            int s = pp / 80; int r = pp - s*80;
            int c = r / 10; int pr = r - c*10;
            int i = I1a[pr], j = J1a[pr];
            int L = Ls[s];
            const float* wa = wls[s] + (i*8 + c)*L;
            const float* wb = wls[s] + (j*8 + c)*L;
            int k0 = h ? (L >> 1) : 0;
            int k1 = h ? L : (L >> 1);
            float af = 0.f, ar = 0.f;
#pragma unroll 8
            for (int k = k0; k < k1; k++) {
                float t = wa[k] - wb[k];
                float df = t + 1e-6f, dr = 1e-6f - t;
                af += df*df; ar += dr*dr;
            }
            sf[u] = af; sr[u] = ar;
        }
        __syncthreads();
        float val = 0.f;
        for (int pp = tid; pp < 320; pp += NT) {
            float ssf = sf[2*pp] + sf[2*pp + 1];
            float ssr = sr[2*pp] + sr[2*pp + 1];
            val += (expf(-sqrtf(ssf)) + expf(-sqrtf(ssr))) * (1.f/200.f);
        }
        sval[tid] = val;
        __syncthreads();
        for (int off = 256; off; off >>= 1) {
            if (tid < off) { sval[tid] += sval[tid+off]; sreg[tid] += sreg[tid+off]; }
            __syncthreads();
        }
        if (tid == 0) out[OFF_LOSS] = 0.1f*(sreg[0]/1600.f) + 0.1f*sval[0];
        __syncthreads();
    }

    // ---- stage x (warps 0-7) and all four w sets (all threads) ----
    {
        int wp_ = tid >> 5, lane = tid & 31;
        if (wp_ < 8) {
            const float* row = x + (b*8 + wp_)*512;
            float v[16]; float sv = 0.f;
#pragma unroll
            for (int i = 0; i < 16; i++) { v[i] = row[lane + 32*i]; sv += v[i]; }
#pragma unroll
            for (int o = 16; o; o >>= 1) sv += __shfl_xor_sync(0xffffffffu, sv, o);
            float mu = sv * (1.f/512.f);
            float qq = 0.f;
#pragma unroll
            for (int i = 0; i < 16; i++) { float d = v[i]-mu; qq += d*d; }
#pragma unroll
            for (int o = 16; o; o >>= 1) qq += __shfl_xor_sync(0xffffffffu, qq, o);
            float sc = 1.f / (sqrtf(qq * (1.f/511.f)) + 1e-8f);
            float* orow = sx + wp_*SXSTR;
#pragma unroll
            for (int i = 0; i < 16; i++) orow[lane + 32*i] = (v[i]-mu)*sc;
            if (lane < SXSTR - 512) orow[512 + lane] = 0.f;
        }
        stage_w<256,260>(sw + SW3, w3, tid);
        stage_w<154,164>(sw + SW2, w2, tid);
        stage_w<103,108>(sw + SW1, w1, tid);
        stage_w< 52, 60>(sw + SW0, w0, tid);
    }
    __syncthreads();

    // ---- barrier-free warp-level work stealing over this batch's T=16 items ----
    {
        int lane = tid & 31;
        for (;;) {
            unsigned wt;
            if (lane == 0) wt = atomicAdd(&g_wt[b], 1u);
            wt = __shfl_sync(0xffffffffu, wt, 0);
            if (wt >= NWT) break;
            int idx = (int)wt*32 + lane;
            if (idx < I3)         item1<256,257,260,120>(sx, sw + SW3, p3, sden, sq, idx);
            else if (idx < I2)    item1<154,359,164, 80>(sx, sw + SW2, p2, sden, sq, idx - I3);
            else if (idx < I1)    item1<103,410,108, 40>(sx, sw + SW1, p1, sden, sq, idx - I2);
            else if (idx < NITEM) item1< 52,461, 60,  0>(sx, sw + SW0, p0, sden, sq, idx - I1);
        }
    }

    // ---- flush block partials ----
    __syncthreads();
    if (tid < NCOL) {
        unsigned dv = sden[tid], qv = sq[tid];
        int gi = b*NCOL + tid;
        if (dv) atomicMax(&g_d[gi], dv);
        if (qv) atomicMax(&g_q[gi], qv);
    }

    // ---- completion counter: last block finalizes ----
    __threadfence();
    __syncthreads();
    if (tid == 0) s_old = atomicAdd(&g_ctr, 1u);
    __syncthreads();
    if (s_old != NBLK - 1) return;

    __threadfence();
    float* sprob = sm;              // [5120]
    float* swout = sm + 5120;       // [1600]
    for (int i = tid; i < NB*NCOL; i += NT) {
        unsigned de = atomicMax(&g_d[i], 0u);   // L2-coherent read
        unsigned qe = atomicMax(&g_q[i], 0u);
        g_d[i] = 0u; g_q[i] = 0u;               // reset for next replay
        float qv = idec(qe);
        float p = expf(-qv*qv);
        out[OFF_DIST + i] = idec(de);
        out[OFF_PROB + i] = p;
        sprob[i] = p;
    }
    for (int i = tid; i < NOUT*NCOL; i += NT) swout[i] = Wout[i];
    __syncthreads();
    for (int tt = tid; tt < NB*NOUT; tt += NT) {
        int bb = tt / NOUT, o = tt - bb*NOUT;
        const float* pr = sprob + bb*NCOL;
        const float* wr = swout + o*NCOL;
        float acc = 0.f;
#pragma unroll 8
        for (int j = 0; j < NCOL; j++) acc += pr[j]*wr[j];
        out[bb*NOUT + o] = acc;
    }
    if (tid < NB) g_wt[tid] = 0u;               // reset counters for replay
    if (tid == 0) g_ctr = 0u;
}

// ---------------- launch ----------------
extern "C" void kernel_launch(void* const* d_in, const int* in_sizes, int n_in,
                              void* d_out, int out_size) {
    const float* x = nullptr;
    const float* w[4] = {nullptr,nullptr,nullptr,nullptr};
    const float* pcm[4] = {nullptr,nullptr,nullptr,nullptr};
    const float* Wout = nullptr;
    for (int i = 0; i < n_in; i++) {
        switch (in_sizes[i]) {
            case 131072: x = (const float*)d_in[i]; break;
            case 2080:  w[0] = (const float*)d_in[i]; break;
            case 4120:  w[1] = (const float*)d_in[i]; break;
            case 6160:  w[2] = (const float*)d_in[i]; break;
            case 10240: w[3] = (const float*)d_in[i]; break;
            case 3688:  pcm[0] = (const float*)d_in[i]; break;
            case 3280:  pcm[1] = (const float*)d_in[i]; break;
            case 2872:  pcm[2] = (const float*)d_in[i]; break;
            case 2056:  pcm[3] = (const float*)d_in[i]; break;
            case 1600:  Wout = (const float*)d_in[i]; break;
            default: break;
        }
    }
    float* out = (float*)d_out;

    cudaFuncSetAttribute(k_all, cudaFuncAttributeMaxDynamicSharedMemorySize, SM_BYTES);

    k_all<<<NBLK, NT, SM_BYTES>>>(x, w[0], w[1], w[2], w[3],
                                  pcm[0], pcm[1], pcm[2], pcm[3], Wout, out);
    (void)out_size;
}

// round 17
// speedup vs baseline: 1.2981x; 1.2981x over previous
#include <cuda_runtime.h>
#include <math.h>

// ---------------- problem constants ----------------
#define NB    32
#define NCOL  160
#define NOUT  10
#define OFF_DIST 320
#define OFF_PROB 5440
#define OFF_LOSS 10560

#define NT    512
#define NBLK  148                 // 1 block per SM; ~4.6 blocks per batch
#define NWT   119                 // warp-tickets per batch (119*32 = 3808 >= 3800 items)
#define NITEM 3800

// smem layout (words)
#define SXSTR 532                 // c*532 %32 = 20c -> conflict-free; max x idx 527
#define SXW   (8*SXSTR)           // 4256
// w regions (T=16 needs WW >= L+4, mult of 4, WW%32 != 0)
#define SW3   0                   // L=256, WW=260
#define SW2   10400               // L=154, WW=164
#define SW1   16960               // L=103, WW=108
#define SW0   21280               // L=52,  WW=60
#define SWTOT 23680
#define SRED  (SXW + SWTOT)       // 27936
#define SM_WORDS (SRED + 320)     // 28256
#define SM_BYTES (SM_WORDS*4)     // 113024 B (1 block/SM)

// item space per batch (expensive-first): set3 [0,680) set2 [680,1600) set1 [1600,2640) set0 [2640,3800)
#define I3 680
#define I2 1600
#define I1 2640

__device__ unsigned g_d[NB*NCOL] = {};
__device__ unsigned g_q[NB*NCOL] = {};
__device__ unsigned g_wt[NB] = {};
__device__ unsigned g_ctr = 0;

__device__ __forceinline__ unsigned fenc(float f){unsigned u=__float_as_uint(f);return (u&0x80000000u)?~u:(u|0x80000000u);}
__device__ __forceinline__ float fdec(unsigned e){unsigned u=(e&0x80000000u)?(e&0x7fffffffu):~e;return __uint_as_float(u);}
__device__ __forceinline__ unsigned ienc(float f){ return ~fenc(f); }   // max(ienc)=min(f); 0 sentinel
__device__ __forceinline__ float idec(unsigned e){ return fdec(~e); }

// ring rotations (compile-time renaming, no MOVs)
#define R0  x0,x1,x2,x3,x4,x5,x6,x7,x8,x9,x10,x11,x12,x13,x14,x15
#define R1  x1,x2,x3,x4,x5,x6,x7,x8,x9,x10,x11,x12,x13,x14,x15,x0
#define R2  x2,x3,x4,x5,x6,x7,x8,x9,x10,x11,x12,x13,x14,x15,x0,x1
#define R3  x3,x4,x5,x6,x7,x8,x9,x10,x11,x12,x13,x14,x15,x0,x1,x2
#define R4  x4,x5,x6,x7,x8,x9,x10,x11,x12,x13,x14,x15,x0,x1,x2,x3
#define R5  x5,x6,x7,x8,x9,x10,x11,x12,x13,x14,x15,x0,x1,x2,x3,x4
#define R6  x6,x7,x8,x9,x10,x11,x12,x13,x14,x15,x0,x1,x2,x3,x4,x5
#define R7  x7,x8,x9,x10,x11,x12,x13,x14,x15,x0,x1,x2,x3,x4,x5,x6
#define R8  x8,x9,x10,x11,x12,x13,x14,x15,x0,x1,x2,x3,x4,x5,x6,x7
#define R9  x9,x10,x11,x12,x13,x14,x15,x0,x1,x2,x3,x4,x5,x6,x7,x8
#define R10 x10,x11,x12,x13,x14,x15,x0,x1,x2,x3,x4,x5,x6,x7,x8,x9
#define R11 x11,x12,x13,x14,x15,x0,x1,x2,x3,x4,x5,x6,x7,x8,x9,x10
#define R12 x12,x13,x14,x15,x0,x1,x2,x3,x4,x5,x6,x7,x8,x9,x10,x11
#define R13 x13,x14,x15,x0,x1,x2,x3,x4,x5,x6,x7,x8,x9,x10,x11,x12
#define R14 x14,x15,x0,x1,x2,x3,x4,x5,x6,x7,x8,x9,x10,x11,x12,x13
#define R15 x15,x0,x1,x2,x3,x4,x5,x6,x7,x8,x9,x10,x11,x12,x13,x14

#define STEP2(W,JJ,a0,a1,a2,a3,a4,a5,a6,a7,a8,a9,aA,aB,aC,aD,aE,aF) do { \
    float w_ = (W); \
    acc0  += fabsf(a0 - w_);  acc1  += fabsf(a1 - w_); \
    acc2  += fabsf(a2 - w_);  acc3  += fabsf(a3 - w_); \
    acc4  += fabsf(a4 - w_);  acc5  += fabsf(a5 - w_); \
    acc6  += fabsf(a6 - w_);  acc7  += fabsf(a7 - w_); \
    acc8  += fabsf(a8 - w_);  acc9  += fabsf(a9 - w_); \
    acc10 += fabsf(aA - w_);  acc11 += fabsf(aB - w_); \
    acc12 += fabsf(aC - w_);  acc13 += fabsf(aD - w_); \
    acc14 += fabsf(aE - w_);  acc15 += fabsf(aF - w_); \
    a0 = xr[(JJ) + 16]; \
} while (0)
#define STEP(W, JJ, RING) STEP2(W, JJ, RING)

#define FIN(K, A) do { \
    int mm = 16*tl + (K); \
    if (mm < M) { \
        float d_ = (A) * INVL * __ldg(&pr[mm]); \
        dmin = fminf(dmin, d_); \
        qmin = fminf(qmin, fabsf(d_)); \
    } \
} while (0)

// ---------------- one item = 16 consecutive windows (validated T=16 core) ----------------
template<int L, int M, int WW, int SBASE>
__device__ __forceinline__ void item1(const float* __restrict__ sx, const float* __restrict__ swr,
                                      const float* __restrict__ pcm,
                                      unsigned* __restrict__ sden, unsigned* __restrict__ sq, int local)
{
    constexpr int MAIN = L & ~15;
    constexpr int REM  = L & 15;
    constexpr float INVL = 1.0f/(float)L;

    int tl = local / 40;
    int nc = local - tl*40;
    int c  = nc & 7;
    const float* xr = sx + c*SXSTR + 16*tl;
    const float* wr = swr + nc*WW;

    float4 xa = *(const float4*)(xr);
    float4 xb = *(const float4*)(xr + 4);
    float4 xc = *(const float4*)(xr + 8);
    float4 xd = *(const float4*)(xr + 12);
    float x0=xa.x,x1=xa.y,x2=xa.z,x3=xa.w, x4=xb.x,x5=xb.y,x6=xb.z,x7=xb.w;
    float x8=xc.x,x9=xc.y,x10=xc.z,x11=xc.w, x12=xd.x,x13=xd.y,x14=xd.z,x15=xd.w;
    float acc0=0.f,acc1=0.f,acc2=0.f,acc3=0.f,acc4=0.f,acc5=0.f,acc6=0.f,acc7=0.f;
    float acc8=0.f,acc9=0.f,acc10=0.f,acc11=0.f,acc12=0.f,acc13=0.f,acc14=0.f,acc15=0.f;

    float4 wA = *(const float4*)(wr);
    for (int j = 0; j < MAIN; j += 16) {
        float4 wB = *(const float4*)(wr + j + 4);
        STEP(wA.x, j+0,  R0);  STEP(wA.y, j+1,  R1);  STEP(wA.z, j+2,  R2);  STEP(wA.w, j+3,  R3);
        float4 wC = *(const float4*)(wr + j + 8);
        STEP(wB.x, j+4,  R4);  STEP(wB.y, j+5,  R5);  STEP(wB.z, j+6,  R6);  STEP(wB.w, j+7,  R7);
        float4 wD = *(const float4*)(wr + j + 12);
        STEP(wC.x, j+8,  R8);  STEP(wC.y, j+9,  R9);  STEP(wC.z, j+10, R10); STEP(wC.w, j+11, R11);
        wA = *(const float4*)(wr + j + 16);   // safe: WW >= L+4
        STEP(wD.x, j+12, R12); STEP(wD.y, j+13, R13); STEP(wD.z, j+14, R14); STEP(wD.w, j+15, R15);
    }
    if (REM > 0) {                            // wA holds wr[MAIN..MAIN+3]
        STEP(wA.x, MAIN+0, R0);
        if (REM > 1) STEP(wA.y, MAIN+1, R1);
        if (REM > 2) STEP(wA.z, MAIN+2, R2);
        if (REM > 3) STEP(wA.w, MAIN+3, R3);
    }
    if (REM > 4) {
        float4 v = *(const float4*)(wr + MAIN + 4);
        STEP(v.x, MAIN+4, R4);
        if (REM > 5) STEP(v.y, MAIN+5, R5);
        if (REM > 6) STEP(v.z, MAIN+6, R6);
        if (REM > 7) STEP(v.w, MAIN+7, R7);
    }
    if (REM > 8) {
        float4 v = *(const float4*)(wr + MAIN + 8);
        STEP(v.x, MAIN+8, R8);
        if (REM > 9)  STEP(v.y, MAIN+9,  R9);
        if (REM > 10) STEP(v.z, MAIN+10, R10);
        if (REM > 11) STEP(v.w, MAIN+11, R11);
    }
    if (REM > 12) {
        float4 v = *(const float4*)(wr + MAIN + 12);
        STEP(v.x, MAIN+12, R12);
        if (REM > 13) STEP(v.y, MAIN+13, R13);
        if (REM > 14) STEP(v.z, MAIN+14, R14);
    }

    const float* pr = pcm + c*M;
    float dmin = 3.4e38f, qmin = 3.4e38f;
    FIN(0,acc0);   FIN(1,acc1);   FIN(2,acc2);   FIN(3,acc3);
    FIN(4,acc4);   FIN(5,acc5);   FIN(6,acc6);   FIN(7,acc7);
    FIN(8,acc8);   FIN(9,acc9);   FIN(10,acc10); FIN(11,acc11);
    FIN(12,acc12); FIN(13,acc13); FIN(14,acc14); FIN(15,acc15);

    atomicMax(&sden[SBASE + nc], ienc(dmin));
    atomicMax(&sq[SBASE + nc],   ienc(qmin));
}

template<int L, int WW>
__device__ __forceinline__ void stage_w(float* __restrict__ dst, const float* __restrict__ wp, int tid) {
    for (int i2 = tid; i2 < 40*L; i2 += NT) {
        int r = i2 / L, j = i2 - r*L;
        dst[r*WW + j] = wp[i2];
    }
}

// ---------------- fused persistent kernel ----------------
__global__ __launch_bounds__(NT, 1)
void k_all(const float* __restrict__ x,
           const float* __restrict__ w0, const float* __restrict__ w1,
           const float* __restrict__ w2, const float* __restrict__ w3,
           const float* __restrict__ p0, const float* __restrict__ p1,
           const float* __restrict__ p2, const float* __restrict__ p3,
           const float* __restrict__ Wout, float* __restrict__ out)
{
    extern __shared__ float sm[];
    float* sx = sm;
    float* sw = sm + SXW;
    unsigned* sden = (unsigned*)(sm + SRED);   // [160]
    unsigned* sq   = sden + 160;               // [160]
    __shared__ unsigned s_old;

    int tid = threadIdx.x;
    int bx = blockIdx.x;
    int b = (bx * NB) / NBLK;                  // ~4.6 blocks per batch

    if (tid < 320) sden[tid] = 0u;             // sden + sq

    // ---- block 0: losses first (uses sm[0..2304) only; x/w staged after) ----
    if (bx == 0) {
        float* sf   = sm;            // [640]
        float* sr   = sm + 640;      // [640]
        float* sval = sm + 1280;     // [512]
        float* sreg = sm + 1792;     // [512]

        float reg = 0.f;
        for (int i = tid; i < NOUT*NCOL; i += NT) reg += fabsf(Wout[i]);
        sreg[tid] = reg;

        const int Ls[4] = {52, 103, 154, 256};
        const float* wls[4] = {w0, w1, w2, w3};
        const signed char I1a[10] = {0,0,0,0,1,1,1,2,2,3};
        const signed char J1a[10] = {1,2,3,4,2,3,4,3,4,4};

        for (int u = tid; u < 640; u += NT) {
            int pp = u >> 1, h = u & 1;
            int s = pp / 80; int r = pp - s*80;
            int c = r / 10; int pr = r - c*10;
            int i = I1a[pr], j = J1a[pr];
            int L = Ls[s];
            const float* wa = wls[s] + (i*8 + c)*L;
            const float* wb = wls[s] + (j*8 + c)*L;
            int k0 = h ? (L >> 1) : 0;
            int k1 = h ? L : (L >> 1);
            float af = 0.f, ar = 0.f;
#pragma unroll 8
            for (int k = k0; k < k1; k++) {
                float t = wa[k] - wb[k];
                float df = t + 1e-6f, dr = 1e-6f - t;
                af += df*df; ar += dr*dr;
            }
            sf[u] = af; sr[u] = ar;
        }
        __syncthreads();
        float val = 0.f;
        for (int pp = tid; pp < 320; pp += NT) {
            float ssf = sf[2*pp] + sf[2*pp + 1];
            float ssr = sr[2*pp] + sr[2*pp + 1];
            val += (expf(-sqrtf(ssf)) + expf(-sqrtf(ssr))) * (1.f/200.f);
        }
        sval[tid] = val;
        __syncthreads();
        for (int off = 256; off; off >>= 1) {
            if (tid < off) { sval[tid] += sval[tid+off]; sreg[tid] += sreg[tid+off]; }
            __syncthreads();
        }
        if (tid == 0) out[OFF_LOSS] = 0.1f*(sreg[0]/1600.f) + 0.1f*sval[0];
        __syncthreads();
    }

    // ---- stage x (warps 0-7) and all four w sets (all threads) ----
    {
        int wp_ = tid >> 5, lane = tid & 31;
        if (wp_ < 8) {
            const float* row = x + (b*8 + wp_)*512;
            float v[16]; float sv = 0.f;
#pragma unroll
            for (int i = 0; i < 16; i++) { v[i] = row[lane + 32*i]; sv += v[i]; }
#pragma unroll
            for (int o = 16; o; o >>= 1) sv += __shfl_xor_sync(0xffffffffu, sv, o);
            float mu = sv * (1.f/512.f);
            float qq = 0.f;
#pragma unroll
            for (int i = 0; i < 16; i++) { float d = v[i]-mu; qq += d*d; }
#pragma unroll
            for (int o = 16; o; o >>= 1) qq += __shfl_xor_sync(0xffffffffu, qq, o);
            float sc = 1.f / (sqrtf(qq * (1.f/511.f)) + 1e-8f);
            float* orow = sx + wp_*SXSTR;
#pragma unroll
            for (int i = 0; i < 16; i++) orow[lane + 32*i] = (v[i]-mu)*sc;
            if (lane < SXSTR - 512) orow[512 + lane] = 0.f;
        }
        stage_w<256,260>(sw + SW3, w3, tid);
        stage_w<154,164>(sw + SW2, w2, tid);
        stage_w<103,108>(sw + SW1, w1, tid);
        stage_w< 52, 60>(sw + SW0, w0, tid);
    }
    __syncthreads();

    // ---- barrier-free warp-level work stealing (expensive-first) ----
    {
        int lane = tid & 31;
        for (;;) {
            unsigned wt;
            if (lane == 0) wt = atomicAdd(&g_wt[b], 1u);
            wt = __shfl_sync(0xffffffffu, wt, 0);
            if (wt >= NWT) break;
            int idx = (int)wt*32 + lane;
            if (idx < I3)         item1<256,257,260,120>(sx, sw + SW3, p3, sden, sq, idx);
            else if (idx < I2)    item1<154,359,164, 80>(sx, sw + SW2, p2, sden, sq, idx - I3);
            else if (idx < I1)    item1<103,410,108, 40>(sx, sw + SW1, p1, sden, sq, idx - I2);
            else if (idx < NITEM) item1< 52,461, 60,  0>(sx, sw + SW0, p0, sden, sq, idx - I1);
        }
    }

    // ---- flush block partials ----
    __syncthreads();
    if (tid < NCOL) {
        unsigned dv = sden[tid], qv = sq[tid];
        int gi = b*NCOL + tid;
        if (dv) atomicMax(&g_d[gi], dv);
        if (qv) atomicMax(&g_q[gi], qv);
    }

    // ---- completion counter: last block finalizes ----
    __threadfence();
    __syncthreads();
    if (tid == 0) s_old = atomicAdd(&g_ctr, 1u);
    __syncthreads();
    if (s_old != NBLK - 1) return;

    __threadfence();
    float* sprob = sm;              // [5120]
    float* swout = sm + 5120;       // [1600]
    for (int i = tid; i < NB*NCOL; i += NT) {
        unsigned de = atomicMax(&g_d[i], 0u);   // L2-coherent read
        unsigned qe = atomicMax(&g_q[i], 0u);
        g_d[i] = 0u; g_q[i] = 0u;               // reset for next replay
        float qv = idec(qe);
        float p = expf(-qv*qv);
        out[OFF_DIST + i] = idec(de);
        out[OFF_PROB + i] = p;
        sprob[i] = p;
    }
    for (int i = tid; i < NOUT*NCOL; i += NT) swout[i] = Wout[i];
    __syncthreads();
    for (int tt = tid; tt < NB*NOUT; tt += NT) {
        int bb = tt / NOUT, o = tt - bb*NOUT;
        const float* pr = sprob + bb*NCOL;
        const float* wr = swout + o*NCOL;
        float acc = 0.f;
#pragma unroll 8
        for (int j = 0; j < NCOL; j++) acc += pr[j]*wr[j];
        out[bb*NOUT + o] = acc;
    }
    if (tid < NB) g_wt[tid] = 0u;               // reset counters for replay
    if (tid == 0) g_ctr = 0u;
}

// ---------------- launch ----------------
extern "C" void kernel_launch(void* const* d_in, const int* in_sizes, int n_in,
                              void* d_out, int out_size) {
    const float* x = nullptr;
    const float* w[4] = {nullptr,nullptr,nullptr,nullptr};
    const float* pcm[4] = {nullptr,nullptr,nullptr,nullptr};
    const float* Wout = nullptr;
    for (int i = 0; i < n_in; i++) {
        switch (in_sizes[i]) {
            case 131072: x = (const float*)d_in[i]; break;
            case 2080:  w[0] = (const float*)d_in[i]; break;
            case 4120:  w[1] = (const float*)d_in[i]; break;
            case 6160:  w[2] = (const float*)d_in[i]; break;
            case 10240: w[3] = (const float*)d_in[i]; break;
            case 3688:  pcm[0] = (const float*)d_in[i]; break;
            case 3280:  pcm[1] = (const float*)d_in[i]; break;
            case 2872:  pcm[2] = (const float*)d_in[i]; break;
            case 2056:  pcm[3] = (const float*)d_in[i]; break;
            case 1600:  Wout = (const float*)d_in[i]; break;
            default: break;
        }
    }
    float* out = (float*)d_out;

    cudaFuncSetAttribute(k_all, cudaFuncAttributeMaxDynamicSharedMemorySize, SM_BYTES);

    k_all<<<NBLK, NT, SM_BYTES>>>(x, w[0], w[1], w[2], w[3],
                                  pcm[0], pcm[1], pcm[2], pcm[3], Wout, out);
    (void)out_size;
}